// round 2
// baseline (speedup 1.0000x reference)
#include <cuda_runtime.h>
#include <math.h>

#define NN 20000
#define EE 640000

typedef unsigned long long ull;

// ---- packed f32x2 helpers (Blackwell fma.rn.f32x2: 2x fp32 FMA per issue) ----
__device__ __forceinline__ ull pk2(float lo, float hi) {
    ull r; asm("mov.b64 %0, {%1, %2};" : "=l"(r) : "f"(lo), "f"(hi)); return r;
}
__device__ __forceinline__ void ffma2(ull& d, ull a, ull b) {
    asm("fma.rn.f32x2 %0, %1, %2, %0;" : "+l"(d) : "l"(a), "l"(b));
}
__device__ __forceinline__ void upk2(ull v, float& a, float& b) {
    asm("mov.b64 {%0, %1}, %2;" : "=f"(a), "=f"(b) : "l"(v));
}

// ------------------------- scratch (device globals; no allocations) ---------
__device__ float g_ef[EE * 8];        // edge bessel*fcut features
__device__ float g_ye[EE * 3];        // sqrt(3)*unit vector per edge
__device__ float g_s[NN * 32];        // scalar features
__device__ float g_v[NN * 96];        // vector features, layout [n][c][f]
__device__ float g_agg[NN * 32 * 4];  // aggregated messages [n][f][{s,v0,v1,v2}]
__device__ float g_gate[NN * 32];     // sigmoid gates

// ------------------------- zero kernels -------------------------------------
__global__ void k_zero_v() {
    int i = blockIdx.x * blockDim.x + threadIdx.x;
    if (i < NN * 96) g_v[i] = 0.f;
}
__global__ void k_zero_agg() {
    int i = blockIdx.x * blockDim.x + threadIdx.x;
    if (i < NN * 128) g_agg[i] = 0.f;
}

// ------------------------- geometry + bessel (once, layer-invariant) --------
__global__ void k_geom(const float* __restrict__ coord, const int* __restrict__ ei) {
    int e = blockIdx.x * blockDim.x + threadIdx.x;
    if (e >= EE) return;
    int sn = ei[e];
    int rc = ei[EE + e];
    float dx = coord[sn * 3 + 0] - coord[rc * 3 + 0];
    float dy = coord[sn * 3 + 1] - coord[rc * 3 + 1];
    float dz = coord[sn * 3 + 2] - coord[rc * 3 + 2];
    float r = sqrtf(dx * dx + dy * dy + dz * dz + 1e-12f);
    float invr = 1.f / r;
    float x = r * 0.2f;  // r / RMAX
    const float SQ3 = 1.7320508075688772f;
    g_ye[e * 3 + 0] = SQ3 * dx * invr;
    g_ye[e * 3 + 1] = SQ3 * dy * invr;
    g_ye[e * 3 + 2] = SQ3 * dz * invr;
    // polynomial cutoff, P=6: 1 - 28 x^6 + 48 x^7 - 21 x^8 (x<1)
    float x3 = x * x * x;
    float x6 = x3 * x3;
    float x7 = x6 * x;
    float x8 = x7 * x;
    float fc = (x < 1.f) ? (1.f - 28.f * x6 + 48.f * x7 - 21.f * x8) : 0.f;
    float pref = 0.6324555320336759f * invr * fc;  // sqrt(2/RMAX)/r * fcut
    const float PI = 3.14159265358979323846f;
#pragma unroll
    for (int b = 0; b < 8; b++) {
        g_ef[e * 8 + b] = pref * sinf((float)(b + 1) * PI * x);
    }
}

// ------------------------- node embedding s = attrs @ W ---------------------
__global__ void k_embed(const float* __restrict__ attrs, const float* __restrict__ W) {
    int i = blockIdx.x * blockDim.x + threadIdx.x;
    if (i >= NN * 32) return;
    int n = i >> 5;
    int f = i & 31;
    float acc = 0.f;
#pragma unroll 8
    for (int a = 0; a < 64; a++) acc += attrs[n * 64 + a] * W[a * 32 + f];
    g_s[i] = acc;
}

// ------------------------- fused radial-MLP + message + scatter -------------
// Block: 64 edges, 256 threads.
//   A) stage W1/b1/W2, ef, ye, indices
//   B) h = silu(ef @ W1 + b1)          (64x64, transposed [k][e] in smem)
//   C) w = h @ W2                      (64x160) register-tiled f32x2 GEMM -> smem
//   D) per-edge message + red.global.add.v4 scatter
#define EDGE_SMEM_FLOATS 26112
__global__ __launch_bounds__(256, 2) void k_edge(const int* __restrict__ ei,
                                                 const float* __restrict__ W1,
                                                 const float* __restrict__ b1,
                                                 const float* __restrict__ W2, int l) {
    extern __shared__ float sm[];
    float* sW1 = sm;            // 512
    float* sb1 = sm + 512;      // 64
    float* sW2 = sm + 576;      // 10240 (64x160)
    float* sh  = sm + 10816;    // 4096  (h transposed [k][e])
    float* sw  = sm + 14912;    // 10240 (w tile [e][160])
    float* sef = sm + 25152;    // 576   (64x9 padded)
    float* sye = sm + 25728;    // 256   (64x4)
    int*   sidx = (int*)(sm + 25984);  // 128 ints
    int t = threadIdx.x;
    int eb = blockIdx.x * 64;
    const float* W1l = W1 + l * 512;
    const float* b1l = b1 + l * 64;
    const float* W2l = W2 + l * 10240;
    for (int i = t; i < 512; i += 256) sW1[i] = W1l[i];
    if (t < 64) sb1[t] = b1l[t];
    for (int i = t; i < 10240; i += 256) sW2[i] = W2l[i];
    for (int i = t; i < 512; i += 256) {
        int e = i >> 3, b = i & 7;
        sef[e * 9 + b] = g_ef[(eb + e) * 8 + b];
    }
    if (t < 192) {
        int e = t / 3, c = t - 3 * e;
        sye[e * 4 + c] = g_ye[(eb + e) * 3 + c];
    }
    if (t < 64) sidx[t] = ei[eb + t];
    else if (t < 128) sidx[t] = ei[EE + eb + (t - 64)];
    __syncthreads();
    // B: hidden layer + silu
    for (int i = t; i < 4096; i += 256) {
        int k = i >> 6, e = i & 63;
        float acc = sb1[k];
#pragma unroll
        for (int b = 0; b < 8; b++) acc += sef[e * 9 + b] * sW1[b * 64 + k];
        sh[k * 64 + e] = acc / (1.f + __expf(-acc));
    }
    __syncthreads();
    // C: 64x160x64 GEMM, thread tile 4 edges x 10 cols (5 f32x2 pairs)
    {
        int tx = t & 15, ty = t >> 4;
        int e0 = ty * 4, c0 = tx * 10;
        ull acc2[4][5];
#pragma unroll
        for (int i = 0; i < 4; i++)
#pragma unroll
            for (int j = 0; j < 5; j++) acc2[i][j] = 0ull;
#pragma unroll 4
        for (int k = 0; k < 64; k++) {
            ull a[4], b[5];
#pragma unroll
            for (int i = 0; i < 4; i++) {
                float av = sh[k * 64 + e0 + i];
                a[i] = pk2(av, av);
            }
#pragma unroll
            for (int j = 0; j < 5; j++) {
                float2 bv = *(const float2*)&sW2[k * 160 + c0 + 2 * j];
                b[j] = pk2(bv.x, bv.y);
            }
#pragma unroll
            for (int i = 0; i < 4; i++)
#pragma unroll
                for (int j = 0; j < 5; j++) ffma2(acc2[i][j], a[i], b[j]);
        }
#pragma unroll
        for (int i = 0; i < 4; i++)
#pragma unroll
            for (int j = 0; j < 5; j++) {
                float x, y;
                upk2(acc2[i][j], x, y);
                sw[(e0 + i) * 160 + c0 + 2 * j] = x;
                sw[(e0 + i) * 160 + c0 + 2 * j + 1] = y;
            }
    }
    __syncthreads();
    // D: message + scatter, warp = edge lane = feature
    int warp = t >> 5, lane = t & 31;
    const float inv = 0.17677669529663687f;  // 1/sqrt(32)
#pragma unroll
    for (int ii = 0; ii < 8; ii++) {
        int el = ii * 8 + warp;
        int sn = sidx[el];
        int rc = sidx[64 + el];
        float y0 = sye[el * 4 + 0];
        float y1 = sye[el * 4 + 1];
        float y2 = sye[el * 4 + 2];
        const float* wp = sw + el * 160;
        float w0 = wp[lane];
        float w1 = wp[32 + lane];
        float w2 = wp[64 + lane];
        float w3 = wp[96 + lane];
        float w4 = wp[128 + lane];
        float sj = g_s[sn * 32 + lane];
        float v0 = g_v[sn * 96 + lane];
        float v1 = g_v[sn * 96 + 32 + lane];
        float v2 = g_v[sn * 96 + 64 + lane];
        float dot = v0 * y0 + v1 * y1 + v2 * y2;
        float cr0 = v1 * y2 - v2 * y1;
        float cr1 = v2 * y0 - v0 * y2;
        float cr2 = v0 * y1 - v1 * y0;
        float ms = (w0 * sj + w3 * dot) * inv;
        float m0 = (w1 * sj * y0 + w2 * v0 + w4 * cr0) * inv;
        float m1 = (w1 * sj * y1 + w2 * v1 + w4 * cr1) * inv;
        float m2 = (w1 * sj * y2 + w2 * v2 + w4 * cr2) * inv;
        float* dst = g_agg + ((long)rc * 32 + lane) * 4;
        asm volatile("red.global.add.v4.f32 [%0], {%1,%2,%3,%4};"
                     :: "l"(dst), "f"(ms), "f"(m0), "f"(m1), "f"(m2)
                     : "memory");
    }
}

// ------------------------- scalar branch node update ------------------------
// pre_s = agg_s @ lin_Ws + einsum('nf,na,fag->ng', s, attrs, sc_Ws)
// Uses per-f Z staging: Z_f[n][a] = s[n,f]*attrs[n,a], then rank-64 update.
#define NS_SMEM_FLOATS 27008
__global__ __launch_bounds__(256, 2) void k_node_s(const float* __restrict__ attrs,
                                                   const float* __restrict__ linWs,
                                                   const float* __restrict__ scWs, int l) {
    extern __shared__ float sm[];
    float* s_sm = sm;             // 128*33 = 4224
    float* at_sm = sm + 4224;     // 128*65 = 8320
    float* lw_sm = sm + 12544;    // 2048
    float* Wch = sm + 14592;      // 4096
    float* Zf = sm + 18688;       // 128*65 = 8320 ; first stages agg as [n*33+f]
    int t = threadIdx.x;
    int nb = blockIdx.x * 128;
    const float* lWs = linWs + l * 2048;
    const float* sWs = scWs + l * 131072;
    for (int i = t; i < 4096; i += 256) {
        int n = i >> 5, f = i & 31;
        bool ok = (nb + n) < NN;
        s_sm[n * 33 + f] = ok ? g_s[(nb + n) * 32 + f] : 0.f;
        Zf[n * 33 + f] = ok ? g_agg[((long)(nb + n) * 32 + f) * 4] : 0.f;
    }
    for (int i = t; i < 8192; i += 256) {
        int n = i >> 6, a = i & 63;
        at_sm[n * 65 + a] = ((nb + n) < NN) ? attrs[(nb + n) * 64 + a] : 0.f;
    }
    for (int i = t; i < 2048; i += 256) lw_sm[i] = lWs[i];
    int tx = t & 15, ty = t >> 4;
    int n0 = ty * 8, c0 = tx * 4;
    ull acc2[8][2];
#pragma unroll
    for (int i = 0; i < 8; i++) { acc2[i][0] = 0ull; acc2[i][1] = 0ull; }
    __syncthreads();
    // lin term (Zf holds agg_s right now)
    for (int f = 0; f < 32; f++) {
        float4 w = *(const float4*)&lw_sm[f * 64 + c0];
        ull wlo = pk2(w.x, w.y), whi = pk2(w.z, w.w);
#pragma unroll
        for (int i = 0; i < 8; i++) {
            float p = Zf[(n0 + i) * 33 + f];
            ull pp = pk2(p, p);
            ffma2(acc2[i][0], pp, wlo);
            ffma2(acc2[i][1], pp, whi);
        }
    }
    // self-connection: stream W slab + Z_f per f
    for (int f = 0; f < 32; f++) {
        __syncthreads();
        const float* slab = sWs + f * 4096;
        for (int i = t; i < 4096; i += 256) Wch[i] = slab[i];
        for (int i = t; i < 8192; i += 256) {
            int n = i >> 6, a = i & 63;
            Zf[n * 65 + a] = s_sm[n * 33 + f] * at_sm[n * 65 + a];
        }
        __syncthreads();
#pragma unroll 2
        for (int a = 0; a < 64; a++) {
            float4 w = *(const float4*)&Wch[a * 64 + c0];
            ull wlo = pk2(w.x, w.y), whi = pk2(w.z, w.w);
#pragma unroll
            for (int i = 0; i < 8; i++) {
                float p = Zf[(n0 + i) * 65 + a];
                ull pp = pk2(p, p);
                ffma2(acc2[i][0], pp, wlo);
                ffma2(acc2[i][1], pp, whi);
            }
        }
    }
#pragma unroll
    for (int i = 0; i < 8; i++) {
        int n = nb + n0 + i;
        if (n >= NN) continue;
        float p[4];
        upk2(acc2[i][0], p[0], p[1]);
        upk2(acc2[i][1], p[2], p[3]);
#pragma unroll
        for (int j = 0; j < 4; j++) {
            int c = c0 + j;
            float pre = p[j];
            if (c < 32) {
                g_s[n * 32 + c] = pre / (1.f + __expf(-pre)) + s_sm[(n0 + i) * 33 + c];
            } else {
                g_gate[n * 32 + (c - 32)] = 1.f / (1.f + __expf(-pre));
            }
        }
    }
}

// ------------------------- vector branch node update ------------------------
// pre_v = agg_v @ lin_Wv + einsum('nfc,na,fag->ngc', v, attrs, sc_Wv)
// v = pre_v * gate + v. Rows m=(n,c), per-f Z staging Z[m][a]=v[m,f]*at[n,a].
#define NV_SMEM_FLOATS 28096
__global__ __launch_bounds__(256, 2) void k_node_v(const float* __restrict__ attrs,
                                                   const float* __restrict__ linWv,
                                                   const float* __restrict__ scWv, int l) {
    extern __shared__ float sm[];
    float* v_sm = sm;              // 64*3*33 = 6336  [(n*3+c)*33+f]
    float* at_sm = sm + 6336;      // 64*65 = 4160
    float* lw_sm = sm + 10496;     // 1024
    float* Wch = sm + 11520;       // 2048
    float* gt_sm = sm + 13568;     // 2048
    float* Z = sm + 15616;         // 192*65 = 12480 ; first stages agg_v [(m)*33+f]
    int t = threadIdx.x;
    int nb = blockIdx.x * 64;
    const float* lW = linWv + l * 1024;
    const float* sW = scWv + l * 65536;
    for (int i = t; i < 64 * 96; i += 256) {
        int n = i / 96, r = i % 96, c = r >> 5, f = r & 31;
        bool ok = (nb + n) < NN;
        v_sm[(n * 3 + c) * 33 + f] = ok ? g_v[(nb + n) * 96 + c * 32 + f] : 0.f;
        Z[(n * 3 + c) * 33 + f] = ok ? g_agg[((long)(nb + n) * 32 + f) * 4 + 1 + c] : 0.f;
    }
    for (int i = t; i < 4096; i += 256) {
        int n = i >> 6, a = i & 63;
        at_sm[n * 65 + a] = ((nb + n) < NN) ? attrs[(nb + n) * 64 + a] : 0.f;
    }
    for (int i = t; i < 2048; i += 256) {
        int n = i >> 5;
        gt_sm[i] = ((nb + n) < NN) ? g_gate[(nb + n) * 32 + (i & 31)] : 0.f;
    }
    for (int i = t; i < 1024; i += 256) lw_sm[i] = lW[i];
    int tx = t & 7, tyR = t >> 3;
    int n0 = tyR * 2, c0 = tx * 4;
    ull acc2[2][3][2];
#pragma unroll
    for (int i = 0; i < 2; i++)
#pragma unroll
        for (int c = 0; c < 3; c++) { acc2[i][c][0] = 0ull; acc2[i][c][1] = 0ull; }
    __syncthreads();
    // lin term (Z holds agg_v)
    for (int f = 0; f < 32; f++) {
        float4 w = *(const float4*)&lw_sm[f * 32 + c0];
        ull wlo = pk2(w.x, w.y), whi = pk2(w.z, w.w);
#pragma unroll
        for (int i = 0; i < 2; i++)
#pragma unroll
            for (int c = 0; c < 3; c++) {
                float p = Z[((n0 + i) * 3 + c) * 33 + f];
                ull pp = pk2(p, p);
                ffma2(acc2[i][c][0], pp, wlo);
                ffma2(acc2[i][c][1], pp, whi);
            }
    }
    // self-connection
    for (int f = 0; f < 32; f++) {
        __syncthreads();
        const float* slab = sW + f * 2048;
        for (int i = t; i < 2048; i += 256) Wch[i] = slab[i];
        for (int i = t; i < 192 * 64; i += 256) {
            int m = i >> 6, a = i & 63;
            Z[m * 65 + a] = v_sm[m * 33 + f] * at_sm[(m / 3) * 65 + a];
        }
        __syncthreads();
#pragma unroll 2
        for (int a = 0; a < 64; a++) {
            float4 w = *(const float4*)&Wch[a * 32 + c0];
            ull wlo = pk2(w.x, w.y), whi = pk2(w.z, w.w);
#pragma unroll
            for (int i = 0; i < 2; i++)
#pragma unroll
                for (int c = 0; c < 3; c++) {
                    float p = Z[((n0 + i) * 3 + c) * 65 + a];
                    ull pp = pk2(p, p);
                    ffma2(acc2[i][c][0], pp, wlo);
                    ffma2(acc2[i][c][1], pp, whi);
                }
        }
    }
#pragma unroll
    for (int i = 0; i < 2; i++) {
        int n = nb + n0 + i;
        if (n >= NN) continue;
#pragma unroll
        for (int c = 0; c < 3; c++) {
            float p[4];
            upk2(acc2[i][c][0], p[0], p[1]);
            upk2(acc2[i][c][1], p[2], p[3]);
#pragma unroll
            for (int j = 0; j < 4; j++) {
                int g = c0 + j;
                g_v[n * 96 + c * 32 + g] = p[j] * gt_sm[(n0 + i) * 32 + g] +
                                           v_sm[((n0 + i) * 3 + c) * 33 + g];
            }
        }
    }
}

// ------------------------- output assembly ----------------------------------
__global__ void k_out(float* __restrict__ out) {
    int i = blockIdx.x * blockDim.x + threadIdx.x;
    if (i >= NN * 128) return;
    int n = i >> 7, c = i & 127;
    float val;
    if (c < 32) {
        val = g_s[n * 32 + c];
    } else {
        int k = c - 32;
        int f = k / 3;
        int cc = k - 3 * f;
        val = g_v[n * 96 + cc * 32 + f];
    }
    out[i] = val;
}

// ------------------------- launch -------------------------------------------
extern "C" void kernel_launch(void* const* d_in, const int* in_sizes, int n_in,
                              void* d_out, int out_size) {
    const float* attrs = (const float*)d_in[0];
    const float* coord = (const float*)d_in[1];
    const int* ei = (const int*)d_in[2];
    const float* embW = (const float*)d_in[3];
    const float* rW1 = (const float*)d_in[4];
    const float* rb1 = (const float*)d_in[5];
    const float* rW2 = (const float*)d_in[6];
    const float* lWs = (const float*)d_in[7];
    const float* lWv = (const float*)d_in[8];
    const float* sWs = (const float*)d_in[9];
    const float* sWv = (const float*)d_in[10];
    (void)in_sizes; (void)n_in; (void)out_size;

    cudaFuncSetAttribute(k_edge, cudaFuncAttributeMaxDynamicSharedMemorySize,
                         EDGE_SMEM_FLOATS * 4);
    cudaFuncSetAttribute(k_node_s, cudaFuncAttributeMaxDynamicSharedMemorySize,
                         NS_SMEM_FLOATS * 4);
    cudaFuncSetAttribute(k_node_v, cudaFuncAttributeMaxDynamicSharedMemorySize,
                         NV_SMEM_FLOATS * 4);

    k_zero_v<<<7500, 256>>>();
    k_geom<<<2500, 256>>>(coord, ei);
    k_embed<<<2500, 256>>>(attrs, embW);
    for (int l = 0; l < 2; l++) {
        k_zero_agg<<<10000, 256>>>();
        k_edge<<<10000, 256, EDGE_SMEM_FLOATS * 4>>>(ei, rW1, rb1, rW2, l);
        k_node_s<<<157, 256, NS_SMEM_FLOATS * 4>>>(attrs, lWs, sWs, l);
        k_node_v<<<313, 256, NV_SMEM_FLOATS * 4>>>(attrs, lWv, sWv, l);
    }
    k_out<<<10000, 256>>>((float*)d_out);
}

// round 7
// speedup vs baseline: 1.1765x; 1.1765x over previous
#include <cuda_runtime.h>
#include <math.h>

#define NN 20000
#define EE 640000

typedef unsigned long long ull;

// ---- packed f32x2 helpers ---------------------------------------------------
__device__ __forceinline__ ull pk2(float lo, float hi) {
    ull r; asm("mov.b64 %0, {%1, %2};" : "=l"(r) : "f"(lo), "f"(hi)); return r;
}
__device__ __forceinline__ void ffma2(ull& d, ull a, ull b) {
    asm("fma.rn.f32x2 %0, %1, %2, %0;" : "+l"(d) : "l"(a), "l"(b));
}
__device__ __forceinline__ void upk2(ull v, float& a, float& b) {
    asm("mov.b64 {%0, %1}, %2;" : "=f"(a), "=f"(b) : "l"(v));
}
// ---- cp.async helpers -------------------------------------------------------
__device__ __forceinline__ void cpa16(float* dst, const float* src) {
    unsigned ds = (unsigned)__cvta_generic_to_shared(dst);
    asm volatile("cp.async.cg.shared.global [%0], [%1], 16;" :: "r"(ds), "l"(src));
}
__device__ __forceinline__ void cpa_commit() {
    asm volatile("cp.async.commit_group;");
}
template <int N> __device__ __forceinline__ void cpa_wait() {
    asm volatile("cp.async.wait_group %0;" :: "n"(N));
}

// ---- scratch (device globals) ----------------------------------------------
__device__ float g_ef[EE * 8];
__device__ float g_ye[EE * 3];
__device__ float g_s[NN * 32];
__device__ float g_v[NN * 96];          // [n][c][f]
__device__ float g_agg[NN * 32 * 4];    // [n][f][{s,v0,v1,v2}]
__device__ float g_pre_s[NN * 64];      // scalar-branch pre-activation
__device__ float g_gate[NN * 32];

// ---- zero kernels -----------------------------------------------------------
__global__ void k_zero_v() {
    int i = blockIdx.x * blockDim.x + threadIdx.x;
    if (i < NN * 24) ((float4*)g_v)[i] = make_float4(0.f, 0.f, 0.f, 0.f);
}
__global__ void k_zero2() {
    int i = blockIdx.x * blockDim.x + threadIdx.x;
    float4 z = make_float4(0.f, 0.f, 0.f, 0.f);
    if (i < NN * 32) ((float4*)g_agg)[i] = z;
    else if (i < NN * 48) ((float4*)g_pre_s)[i - NN * 32] = z;
}

// ---- geometry + bessel ------------------------------------------------------
__global__ void k_geom(const float* __restrict__ coord, const int* __restrict__ ei) {
    int e = blockIdx.x * blockDim.x + threadIdx.x;
    if (e >= EE) return;
    int sn = ei[e], rc = ei[EE + e];
    float dx = coord[sn * 3 + 0] - coord[rc * 3 + 0];
    float dy = coord[sn * 3 + 1] - coord[rc * 3 + 1];
    float dz = coord[sn * 3 + 2] - coord[rc * 3 + 2];
    float r = sqrtf(dx * dx + dy * dy + dz * dz + 1e-12f);
    float invr = 1.f / r;
    float x = r * 0.2f;
    const float SQ3 = 1.7320508075688772f;
    g_ye[e * 3 + 0] = SQ3 * dx * invr;
    g_ye[e * 3 + 1] = SQ3 * dy * invr;
    g_ye[e * 3 + 2] = SQ3 * dz * invr;
    float x3 = x * x * x, x6 = x3 * x3, x7 = x6 * x, x8 = x7 * x;
    float fc = (x < 1.f) ? (1.f - 28.f * x6 + 48.f * x7 - 21.f * x8) : 0.f;
    float pref = 0.6324555320336759f * invr * fc;
    const float PI = 3.14159265358979323846f;
#pragma unroll
    for (int b = 0; b < 8; b++)
        g_ef[e * 8 + b] = pref * sinf((float)(b + 1) * PI * x);
}

// ---- node embedding ---------------------------------------------------------
__global__ void k_embed(const float* __restrict__ attrs, const float* __restrict__ W) {
    int i = blockIdx.x * blockDim.x + threadIdx.x;
    if (i >= NN * 32) return;
    int n = i >> 5, f = i & 31;
    float acc = 0.f;
#pragma unroll 8
    for (int a = 0; a < 64; a++) acc += attrs[n * 64 + a] * W[a * 32 + f];
    g_s[i] = acc;
}

// ---- fused radial-MLP + message + scatter (128 edges/block) -----------------
#define SH_STR 66
#define EDGE_SMEM_FLOATS (512 + 64 + 10240 + 128 * SH_STR + 20480 + 1152 + 512 + 256)
__global__ __launch_bounds__(256, 1) void k_edge(const int* __restrict__ ei,
                                                 const float* __restrict__ W1,
                                                 const float* __restrict__ b1,
                                                 const float* __restrict__ W2, int l) {
    extern __shared__ float sm[];
    float* sW1 = sm;                          // 512
    float* sb1 = sm + 512;                    // 64
    float* sW2 = sm + 576;                    // 10240
    float* sh  = sm + 10816;                  // 128*66
    float* sw  = sm + 10816 + 128 * SH_STR;   // 20480
    float* sef = sw + 20480;                  // 1152 (128x9)
    float* sye = sef + 1152;                  // 512  (128x4)
    int*   sidx = (int*)(sye + 512);          // 256
    int t = threadIdx.x;
    int eb = blockIdx.x * 128;
    const float* W1l = W1 + l * 512;
    const float* b1l = b1 + l * 64;
    const float* W2l = W2 + l * 10240;
    for (int i = t; i < 512; i += 256) sW1[i] = W1l[i];
    if (t < 64) sb1[t] = b1l[t];
    for (int i = t; i < 2560; i += 256)
        ((float4*)sW2)[i] = ((const float4*)W2l)[i];
    for (int i = t; i < 1024; i += 256) {
        int e = i >> 3, b = i & 7;
        sef[e * 9 + b] = g_ef[(eb + e) * 8 + b];
    }
    for (int i = t; i < 384; i += 256) {
        int e = i / 3, c = i - 3 * e;
        sye[e * 4 + c] = g_ye[(eb + e) * 3 + c];
    }
    if (t < 128) sidx[t] = ei[eb + t];
    else if (t < 256) sidx[t] = ei[EE + eb + (t - 128)];
    __syncthreads();
    // hidden layer + silu: [e][k] layout
    for (int i = t; i < 8192; i += 256) {
        int k = i & 63, e = i >> 6;
        float acc = sb1[k];
#pragma unroll
        for (int b = 0; b < 8; b++) acc += sef[e * 9 + b] * sW1[b * 64 + k];
        sh[e * SH_STR + k] = acc / (1.f + __expf(-acc));
    }
    __syncthreads();
    // GEMM 128x160x64: thread tile 8 edges x 10 cols, k-pairs
    {
        int tx = t & 15, ty = t >> 4;
        int e0 = ty * 8, c0 = tx * 10;
        ull acc[8][5];
#pragma unroll
        for (int i = 0; i < 8; i++)
#pragma unroll
            for (int j = 0; j < 5; j++) acc[i][j] = 0ull;
        for (int kp = 0; kp < 32; kp++) {
            int k2 = kp * 2;
            const float* bp0 = sW2 + k2 * 160 + c0;
            ull b0[5], b1v[5];
#pragma unroll
            for (int j = 0; j < 5; j++) {
                b0[j] = *(const ull*)(bp0 + 2 * j);
                b1v[j] = *(const ull*)(bp0 + 160 + 2 * j);
            }
#pragma unroll
            for (int i = 0; i < 8; i++) {
                float2 hv = *(const float2*)&sh[(e0 + i) * SH_STR + k2];
                ull a0 = pk2(hv.x, hv.x), a1 = pk2(hv.y, hv.y);
#pragma unroll
                for (int j = 0; j < 5; j++) {
                    ffma2(acc[i][j], a0, b0[j]);
                    ffma2(acc[i][j], a1, b1v[j]);
                }
            }
        }
#pragma unroll
        for (int i = 0; i < 8; i++)
#pragma unroll
            for (int j = 0; j < 5; j++)
                *(ull*)&sw[(e0 + i) * 160 + c0 + 2 * j] = acc[i][j];
    }
    __syncthreads();
    // message + scatter: 8 warps x 16 edges
    int warp = t >> 5, lane = t & 31;
    const float inv = 0.17677669529663687f;
#pragma unroll 2
    for (int ii = 0; ii < 16; ii++) {
        int el = warp * 16 + ii;
        int sn = sidx[el];
        int rc = sidx[128 + el];
        float y0 = sye[el * 4 + 0];
        float y1 = sye[el * 4 + 1];
        float y2 = sye[el * 4 + 2];
        const float* wp = sw + el * 160;
        float w0 = wp[lane];
        float w1 = wp[32 + lane];
        float w2 = wp[64 + lane];
        float w3 = wp[96 + lane];
        float w4 = wp[128 + lane];
        float sj = __ldg(&g_s[sn * 32 + lane]);
        float v0 = __ldg(&g_v[sn * 96 + lane]);
        float v1 = __ldg(&g_v[sn * 96 + 32 + lane]);
        float v2 = __ldg(&g_v[sn * 96 + 64 + lane]);
        float dot = v0 * y0 + v1 * y1 + v2 * y2;
        float cr0 = v1 * y2 - v2 * y1;
        float cr1 = v2 * y0 - v0 * y2;
        float cr2 = v0 * y1 - v1 * y0;
        float ms = (w0 * sj + w3 * dot) * inv;
        float m0 = (w1 * sj * y0 + w2 * v0 + w4 * cr0) * inv;
        float m1 = (w1 * sj * y1 + w2 * v1 + w4 * cr1) * inv;
        float m2 = (w1 * sj * y2 + w2 * v2 + w4 * cr2) * inv;
        float* dst = g_agg + ((long)rc * 32 + lane) * 4;
        asm volatile("red.global.add.v4.f32 [%0], {%1,%2,%3,%4};"
                     :: "l"(dst), "f"(ms), "f"(m0), "f"(m1), "f"(m2)
                     : "memory");
    }
}

// ---- scalar branch: partial pre_s, f-split across blockIdx.y ----------------
#define NS_SMEM_FLOATS 29056
__global__ __launch_bounds__(256, 1) void k_node_s(const float* __restrict__ attrs,
                                                   const float* __restrict__ linWs,
                                                   const float* __restrict__ scWs, int l) {
    extern __shared__ float sm[];
    float* at_sm = sm;            // 128*65
    float* s_sm = sm + 8320;      // 128*17
    float* Zf = sm + 10496;       // 128*65
    float* lw = sm + 18816;       // 2048
    float* Wbuf = sm + 20864;     // 2*4096
    int t = threadIdx.x;
    int nb = blockIdx.x * 128;
    int chunk = blockIdx.y;
    int f0 = chunk * 16;
    const float* lWs = linWs + l * 2048;
    const float* sWs = scWs + l * 131072;
    for (int i = t; i < 8192; i += 256) {
        int n = i >> 6, a = i & 63;
        at_sm[n * 65 + a] = ((nb + n) < NN) ? attrs[(nb + n) * 64 + a] : 0.f;
    }
    for (int i = t; i < 2048; i += 256) {
        int n = i >> 4, fl = i & 15;
        s_sm[n * 17 + fl] = ((nb + n) < NN) ? g_s[(nb + n) * 32 + f0 + fl] : 0.f;
    }
    if (chunk == 0) {
        for (int i = t; i < 4096; i += 256) {
            int n = i >> 5, f = i & 31;
            Zf[n * 33 + f] = ((nb + n) < NN) ? g_agg[((long)(nb + n) * 32 + f) * 4] : 0.f;
        }
        for (int i = t; i < 2048; i += 256) lw[i] = lWs[i];
    }
    {
        const float* src = sWs + (long)f0 * 4096;
        for (int k = 0; k < 4; k++)
            cpa16(Wbuf + (t + k * 256) * 4, src + (t + k * 256) * 4);
        cpa_commit();
    }
    int tx = t & 15, ty = t >> 4;
    int n0 = ty * 8, c0 = tx * 4;
    ull acc[8][2];
#pragma unroll
    for (int i = 0; i < 8; i++) { acc[i][0] = 0ull; acc[i][1] = 0ull; }
    __syncthreads();
    if (chunk == 0) {
        for (int f = 0; f < 32; f++) {
            float4 w = *(const float4*)&lw[f * 64 + c0];
            ull wlo = pk2(w.x, w.y), whi = pk2(w.z, w.w);
#pragma unroll
            for (int i = 0; i < 8; i++) {
                float p = Zf[(n0 + i) * 33 + f];
                ull pp = pk2(p, p);
                ffma2(acc[i][0], pp, wlo);
                ffma2(acc[i][1], pp, whi);
            }
        }
    }
    for (int fi = 0; fi < 16; fi++) {
        __syncthreads();
        if (fi + 1 < 16) {
            float* dst = Wbuf + ((fi + 1) & 1) * 4096;
            const float* src = sWs + (long)(f0 + fi + 1) * 4096;
            for (int k = 0; k < 4; k++)
                cpa16(dst + (t + k * 256) * 4, src + (t + k * 256) * 4);
            cpa_commit();
        }
        for (int i = t; i < 8192; i += 256) {
            int n = i >> 6, a = i & 63;
            Zf[n * 65 + a] = s_sm[n * 17 + fi] * at_sm[n * 65 + a];
        }
        if (fi + 1 < 16) cpa_wait<1>(); else cpa_wait<0>();
        __syncthreads();
        const float* W = Wbuf + (fi & 1) * 4096;
#pragma unroll 2
        for (int a = 0; a < 64; a++) {
            float4 w = *(const float4*)&W[a * 64 + c0];
            ull wlo = pk2(w.x, w.y), whi = pk2(w.z, w.w);
#pragma unroll
            for (int i = 0; i < 8; i++) {
                float p = Zf[(n0 + i) * 65 + a];
                ull pp = pk2(p, p);
                ffma2(acc[i][0], pp, wlo);
                ffma2(acc[i][1], pp, whi);
            }
        }
    }
#pragma unroll
    for (int i = 0; i < 8; i++) {
        int n = nb + n0 + i;
        if (n >= NN) continue;
        float p0, p1, p2, p3;
        upk2(acc[i][0], p0, p1);
        upk2(acc[i][1], p2, p3);
        float* dst = g_pre_s + (long)n * 64 + c0;
        asm volatile("red.global.add.v4.f32 [%0], {%1,%2,%3,%4};"
                     :: "l"(dst), "f"(p0), "f"(p1), "f"(p2), "f"(p3)
                     : "memory");
    }
}

// ---- scalar finalize --------------------------------------------------------
__global__ void k_fin_s() {
    int i = blockIdx.x * blockDim.x + threadIdx.x;
    if (i >= NN * 32) return;
    int n = i >> 5, f = i & 31;
    float a = g_pre_s[n * 64 + f];
    float b = g_pre_s[n * 64 + 32 + f];
    g_gate[i] = 1.f / (1.f + __expf(-b));
    g_s[i] = g_s[i] + a / (1.f + __expf(-a));
}

// ---- vector branch: T-factorized einsum -------------------------------------
#define NV_SMEM_FLOATS 45504
__global__ __launch_bounds__(256, 1) void k_node_v(const float* __restrict__ attrs,
                                                   const float* __restrict__ linWv,
                                                   const float* __restrict__ scWv, int l) {
    extern __shared__ float sm[];
    float* at_sm = sm;            // 64*65
    float* v_sm = sm + 4160;      // 192*33
    float* av_sm = sm + 10496;    // 192*33
    float* T = sm + 16832;        // 256*36
    float* lw = sm + 26048;       // 1024
    float* gt_sm = sm + 27072;    // 2048
    float* Wbuf = sm + 29120;     // 2*8192
    int t = threadIdx.x;
    int nb = blockIdx.x * 64;
    const float* lW = linWv + l * 1024;
    const float* sW = scWv + l * 65536;
    for (int i = t; i < 64 * 96; i += 256) {
        int n = i / 96, r = i % 96, c = r >> 5, f = r & 31;
        bool ok = (nb + n) < NN;
        v_sm[(n * 3 + c) * 33 + f] = ok ? g_v[(nb + n) * 96 + c * 32 + f] : 0.f;
        av_sm[(n * 3 + c) * 33 + f] = ok ? g_agg[((long)(nb + n) * 32 + f) * 4 + 1 + c] : 0.f;
    }
    for (int i = t; i < 4096; i += 256) {
        int n = i >> 6, a = i & 63;
        at_sm[n * 65 + a] = ((nb + n) < NN) ? attrs[(nb + n) * 64 + a] : 0.f;
    }
    for (int i = t; i < 2048; i += 256) {
        int n = i >> 5;
        gt_sm[i] = ((nb + n) < NN) ? g_gate[(nb + n) * 32 + (i & 31)] : 0.f;
    }
    for (int i = t; i < 1024; i += 256) lw[i] = lW[i];
    {
        for (int k = 0; k < 8; k++)
            cpa16(Wbuf + (t + k * 256) * 4, sW + (t + k * 256) * 4);
        cpa_commit();
    }
    int tyB = t >> 3;
    int g0 = (t & 7) * 4;
    int n0 = tyB * 2;
    ull acc[2][3][2];
#pragma unroll
    for (int i = 0; i < 2; i++)
#pragma unroll
        for (int c = 0; c < 3; c++) { acc[i][c][0] = 0ull; acc[i][c][1] = 0ull; }
    __syncthreads();
    for (int f = 0; f < 32; f++) {
        float4 w = *(const float4*)&lw[f * 32 + g0];
        ull wlo = pk2(w.x, w.y), whi = pk2(w.z, w.w);
#pragma unroll
        for (int i = 0; i < 2; i++)
#pragma unroll
            for (int c = 0; c < 3; c++) {
                float p = av_sm[((n0 + i) * 3 + c) * 33 + f];
                ull pp = pk2(p, p);
                ffma2(acc[i][c][0], pp, wlo);
                ffma2(acc[i][c][1], pp, whi);
            }
    }
    int fl1 = tyB >> 3;
    int n0p = (tyB & 7) * 8;
    for (int ch = 0; ch < 8; ch++) {
        __syncthreads();
        if (ch + 1 < 8) {
            float* dst = Wbuf + ((ch + 1) & 1) * 8192;
            const float* src = sW + (long)(ch + 1) * 8192;
            for (int k = 0; k < 8; k++)
                cpa16(dst + (t + k * 256) * 4, src + (t + k * 256) * 4);
            cpa_commit();
        }
        if (ch + 1 < 8) cpa_wait<1>(); else cpa_wait<0>();
        __syncthreads();
        {
            const float* W = Wbuf + (ch & 1) * 8192;
            ull tacc[8][2];
#pragma unroll
            for (int i = 0; i < 8; i++) { tacc[i][0] = 0ull; tacc[i][1] = 0ull; }
#pragma unroll 2
            for (int a = 0; a < 64; a++) {
                float4 w = *(const float4*)&W[(fl1 * 64 + a) * 32 + g0];
                ull wlo = pk2(w.x, w.y), whi = pk2(w.z, w.w);
#pragma unroll
                for (int i = 0; i < 8; i++) {
                    float p = at_sm[(n0p + i) * 65 + a];
                    ull pp = pk2(p, p);
                    ffma2(tacc[i][0], pp, wlo);
                    ffma2(tacc[i][1], pp, whi);
                }
            }
#pragma unroll
            for (int i = 0; i < 8; i++) {
                float p0, p1, p2, p3;
                upk2(tacc[i][0], p0, p1);
                upk2(tacc[i][1], p2, p3);
                *(float4*)&T[((n0p + i) * 4 + fl1) * 36 + g0] = make_float4(p0, p1, p2, p3);
            }
        }
        __syncthreads();
#pragma unroll
        for (int fl = 0; fl < 4; fl++) {
            int f = ch * 4 + fl;
#pragma unroll
            for (int i = 0; i < 2; i++) {
                const float* Tr = &T[((n0 + i) * 4 + fl) * 36 + g0];
                ull t0 = *(const ull*)Tr;
                ull t1 = *(const ull*)(Tr + 2);
#pragma unroll
                for (int c = 0; c < 3; c++) {
                    float p = v_sm[((n0 + i) * 3 + c) * 33 + f];
                    ull pp = pk2(p, p);
                    ffma2(acc[i][c][0], pp, t0);
                    ffma2(acc[i][c][1], pp, t1);
                }
            }
        }
    }
#pragma unroll
    for (int i = 0; i < 2; i++) {
        int n = nb + n0 + i;
        if (n >= NN) continue;
#pragma unroll
        for (int c = 0; c < 3; c++) {
            float p0, p1, p2, p3;
            upk2(acc[i][c][0], p0, p1);
            upk2(acc[i][c][1], p2, p3);
            float4 o;
            o.x = p0 * gt_sm[(n0 + i) * 32 + g0 + 0] + v_sm[((n0 + i) * 3 + c) * 33 + g0 + 0];
            o.y = p1 * gt_sm[(n0 + i) * 32 + g0 + 1] + v_sm[((n0 + i) * 3 + c) * 33 + g0 + 1];
            o.z = p2 * gt_sm[(n0 + i) * 32 + g0 + 2] + v_sm[((n0 + i) * 3 + c) * 33 + g0 + 2];
            o.w = p3 * gt_sm[(n0 + i) * 32 + g0 + 3] + v_sm[((n0 + i) * 3 + c) * 33 + g0 + 3];
            *(float4*)&g_v[(long)n * 96 + c * 32 + g0] = o;
        }
    }
}

// ---- output assembly --------------------------------------------------------
__global__ void k_out(float* __restrict__ out) {
    int i = blockIdx.x * blockDim.x + threadIdx.x;
    if (i >= NN * 128) return;
    int n = i >> 7, c = i & 127;
    float val;
    if (c < 32) {
        val = g_s[n * 32 + c];
    } else {
        int k = c - 32;
        int f = k / 3;
        int cc = k - 3 * f;
        val = g_v[n * 96 + cc * 32 + f];
    }
    out[i] = val;
}

// ---- launch -----------------------------------------------------------------
extern "C" void kernel_launch(void* const* d_in, const int* in_sizes, int n_in,
                              void* d_out, int out_size) {
    const float* attrs = (const float*)d_in[0];
    const float* coord = (const float*)d_in[1];
    const int* ei = (const int*)d_in[2];
    const float* embW = (const float*)d_in[3];
    const float* rW1 = (const float*)d_in[4];
    const float* rb1 = (const float*)d_in[5];
    const float* rW2 = (const float*)d_in[6];
    const float* lWs = (const float*)d_in[7];
    const float* lWv = (const float*)d_in[8];
    const float* sWs = (const float*)d_in[9];
    const float* sWv = (const float*)d_in[10];
    (void)in_sizes; (void)n_in; (void)out_size;

    cudaFuncSetAttribute(k_edge, cudaFuncAttributeMaxDynamicSharedMemorySize,
                         EDGE_SMEM_FLOATS * 4);
    cudaFuncSetAttribute(k_node_s, cudaFuncAttributeMaxDynamicSharedMemorySize,
                         NS_SMEM_FLOATS * 4);
    cudaFuncSetAttribute(k_node_v, cudaFuncAttributeMaxDynamicSharedMemorySize,
                         NV_SMEM_FLOATS * 4);

    k_zero_v<<<1875, 256>>>();
    k_geom<<<2500, 256>>>(coord, ei);
    k_embed<<<2500, 256>>>(attrs, embW);
    for (int l = 0; l < 2; l++) {
        k_zero2<<<3750, 256>>>();
        k_edge<<<5000, 256, EDGE_SMEM_FLOATS * 4>>>(ei, rW1, rb1, rW2, l);
        dim3 gs(157, 2);
        k_node_s<<<gs, 256, NS_SMEM_FLOATS * 4>>>(attrs, lWs, sWs, l);
        k_fin_s<<<2500, 256>>>();
        k_node_v<<<313, 256, NV_SMEM_FLOATS * 4>>>(attrs, lWv, sWv, l);
    }
    k_out<<<10000, 256>>>((float*)d_out);
}

// round 9
// speedup vs baseline: 1.3101x; 1.1135x over previous
#include <cuda_runtime.h>
#include <math.h>

#define NN 20000
#define EE 640000

typedef unsigned long long ull;

// ---- packed f32x2 helpers ---------------------------------------------------
__device__ __forceinline__ ull pk2(float lo, float hi) {
    ull r; asm("mov.b64 %0, {%1, %2};" : "=l"(r) : "f"(lo), "f"(hi)); return r;
}
__device__ __forceinline__ void ffma2(ull& d, ull a, ull b) {
    asm("fma.rn.f32x2 %0, %1, %2, %0;" : "+l"(d) : "l"(a), "l"(b));
}
__device__ __forceinline__ void upk2(ull v, float& a, float& b) {
    asm("mov.b64 {%0, %1}, %2;" : "=f"(a), "=f"(b) : "l"(v));
}
// ---- cp.async helpers -------------------------------------------------------
__device__ __forceinline__ void cpa16(float* dst, const float* src) {
    unsigned ds = (unsigned)__cvta_generic_to_shared(dst);
    asm volatile("cp.async.cg.shared.global [%0], [%1], 16;" :: "r"(ds), "l"(src));
}
__device__ __forceinline__ void cpa_commit() {
    asm volatile("cp.async.commit_group;");
}
template <int N> __device__ __forceinline__ void cpa_wait() {
    asm volatile("cp.async.wait_group %0;" :: "n"(N));
}

// ---- scratch (device globals) ----------------------------------------------
__device__ float g_ef[EE * 8];
__device__ float g_ye[EE * 3];
__device__ float g_s[NN * 32];
__device__ float g_v[NN * 96];          // [n][c][f]
__device__ float g_agg[NN * 32 * 4];    // [n][f][{s,v0,v1,v2}]
__device__ float g_pre_s[NN * 64];      // scalar-branch pre-activation
__device__ float g_gate[NN * 32];

// ---- zero kernels -----------------------------------------------------------
__global__ void k_zero_v() {
    int i = blockIdx.x * blockDim.x + threadIdx.x;
    if (i < NN * 24) ((float4*)g_v)[i] = make_float4(0.f, 0.f, 0.f, 0.f);
}
__global__ void k_zero2() {
    int i = blockIdx.x * blockDim.x + threadIdx.x;
    float4 z = make_float4(0.f, 0.f, 0.f, 0.f);
    if (i < NN * 32) ((float4*)g_agg)[i] = z;
    else if (i < NN * 48) ((float4*)g_pre_s)[i - NN * 32] = z;
}

// ---- geometry + bessel ------------------------------------------------------
__global__ void k_geom(const float* __restrict__ coord, const int* __restrict__ ei) {
    int e = blockIdx.x * blockDim.x + threadIdx.x;
    if (e >= EE) return;
    int sn = ei[e], rc = ei[EE + e];
    float dx = coord[sn * 3 + 0] - coord[rc * 3 + 0];
    float dy = coord[sn * 3 + 1] - coord[rc * 3 + 1];
    float dz = coord[sn * 3 + 2] - coord[rc * 3 + 2];
    float r = sqrtf(dx * dx + dy * dy + dz * dz + 1e-12f);
    float invr = 1.f / r;
    float x = r * 0.2f;
    const float SQ3 = 1.7320508075688772f;
    g_ye[e * 3 + 0] = SQ3 * dx * invr;
    g_ye[e * 3 + 1] = SQ3 * dy * invr;
    g_ye[e * 3 + 2] = SQ3 * dz * invr;
    float x3 = x * x * x, x6 = x3 * x3, x7 = x6 * x, x8 = x7 * x;
    float fc = (x < 1.f) ? (1.f - 28.f * x6 + 48.f * x7 - 21.f * x8) : 0.f;
    float pref = 0.6324555320336759f * invr * fc;
    const float PI = 3.14159265358979323846f;
#pragma unroll
    for (int b = 0; b < 8; b++)
        g_ef[e * 8 + b] = pref * sinf((float)(b + 1) * PI * x);
}

// ---- node embedding ---------------------------------------------------------
__global__ void k_embed(const float* __restrict__ attrs, const float* __restrict__ W) {
    int i = blockIdx.x * blockDim.x + threadIdx.x;
    if (i >= NN * 32) return;
    int n = i >> 5, f = i & 31;
    float acc = 0.f;
#pragma unroll 8
    for (int a = 0; a < 64; a++) acc += attrs[n * 64 + a] * W[a * 32 + f];
    g_s[i] = acc;
}

// ---- fused radial-MLP + message + scatter (128 edges/block, 2 CTAs/SM) ------
// GEMM output stays in registers in scatter layout: warp owns 16 edges,
// lane ln computes w[e][p*32+ln] for p=0..4 (edge-paired f32x2 accumulators).
#define SH_STR 66
#define EDGE_SMEM_FLOATS (512 + 64 + 10240 + 128 * SH_STR + 1152 + 512 + 256)
__global__ __launch_bounds__(256, 2) void k_edge(const int* __restrict__ ei,
                                                 const float* __restrict__ W1,
                                                 const float* __restrict__ b1,
                                                 const float* __restrict__ W2, int l) {
    extern __shared__ float sm[];
    float* sW1 = sm;                    // 512
    float* sb1 = sm + 512;              // 64
    float* sW2 = sm + 576;              // 10240 (64x160)
    float* sh  = sm + 10816;            // 128*66
    float* sef = sm + 10816 + 128 * SH_STR;  // 1152 (128x9)
    float* sye = sef + 1152;            // 512  (128x4)
    int*   sidx = (int*)(sye + 512);    // 256
    int t = threadIdx.x;
    int eb = blockIdx.x * 128;
    const float* W1l = W1 + l * 512;
    const float* b1l = b1 + l * 64;
    const float* W2l = W2 + l * 10240;
    // async-stage W2 (overlapped with staging + hidden compute)
    for (int i = t; i < 2560; i += 256)
        cpa16(sW2 + i * 4, W2l + i * 4);
    cpa_commit();
    for (int i = t; i < 512; i += 256) sW1[i] = W1l[i];
    if (t < 64) sb1[t] = b1l[t];
    for (int i = t; i < 1024; i += 256) {
        int e = i >> 3, b = i & 7;
        sef[e * 9 + b] = g_ef[(eb + e) * 8 + b];
    }
    for (int i = t; i < 384; i += 256) {
        int e = i / 3, c = i - 3 * e;
        sye[e * 4 + c] = g_ye[(eb + e) * 3 + c];
    }
    if (t < 128) sidx[t] = ei[eb + t];
    else if (t < 256) sidx[t] = ei[EE + eb + (t - 128)];
    __syncthreads();
    // hidden layer + silu: [e][k] layout
    for (int i = t; i < 8192; i += 256) {
        int k = i & 63, e = i >> 6;
        float acc = sb1[k];
#pragma unroll
        for (int b = 0; b < 8; b++) acc += sef[e * 9 + b] * sW1[b * 64 + k];
        sh[e * SH_STR + k] = acc / (1.f + __expf(-acc));
    }
    cpa_wait<0>();
    __syncthreads();
    // GEMM: warp = 16 edges, lane = output column within each path
    int warp = t >> 5, lane = t & 31;
    int ebase = warp * 16;
    ull acc[5][8];
#pragma unroll
    for (int p = 0; p < 5; p++)
#pragma unroll
        for (int j = 0; j < 8; j++) acc[p][j] = 0ull;
    {
        const float* shw = sh + ebase * SH_STR;
        for (int k = 0; k < 64; k++) {
            const float* bp = sW2 + k * 160 + lane;
            float b0 = bp[0], b1v = bp[32], b2 = bp[64], b3 = bp[96], b4 = bp[128];
            ull B0 = pk2(b0, b0), B1 = pk2(b1v, b1v), B2 = pk2(b2, b2);
            ull B3 = pk2(b3, b3), B4 = pk2(b4, b4);
            const float* ar = shw + k;
#pragma unroll
            for (int j = 0; j < 8; j++) {
                float a0 = ar[(2 * j) * SH_STR];
                float a1 = ar[(2 * j + 1) * SH_STR];
                ull aa = pk2(a0, a1);
                ffma2(acc[0][j], aa, B0);
                ffma2(acc[1][j], aa, B1);
                ffma2(acc[2][j], aa, B2);
                ffma2(acc[3][j], aa, B3);
                ffma2(acc[4][j], aa, B4);
            }
        }
    }
    // scatter: w values live in acc registers
    const float inv = 0.17677669529663687f;
#pragma unroll
    for (int j = 0; j < 8; j++) {
        float wl[5], wh[5];
#pragma unroll
        for (int p = 0; p < 5; p++) upk2(acc[p][j], wl[p], wh[p]);
#pragma unroll
        for (int s = 0; s < 2; s++) {
            int el = ebase + 2 * j + s;
            const float* w = s ? wh : wl;
            int sn = sidx[el];
            int rc = sidx[128 + el];
            float y0 = sye[el * 4 + 0];
            float y1 = sye[el * 4 + 1];
            float y2 = sye[el * 4 + 2];
            float sj = __ldg(&g_s[sn * 32 + lane]);
            float v0 = __ldg(&g_v[sn * 96 + lane]);
            float v1 = __ldg(&g_v[sn * 96 + 32 + lane]);
            float v2 = __ldg(&g_v[sn * 96 + 64 + lane]);
            float dot = v0 * y0 + v1 * y1 + v2 * y2;
            float cr0 = v1 * y2 - v2 * y1;
            float cr1 = v2 * y0 - v0 * y2;
            float cr2 = v0 * y1 - v1 * y0;
            float ms = (w[0] * sj + w[3] * dot) * inv;
            float m0 = (w[1] * sj * y0 + w[2] * v0 + w[4] * cr0) * inv;
            float m1 = (w[1] * sj * y1 + w[2] * v1 + w[4] * cr1) * inv;
            float m2 = (w[1] * sj * y2 + w[2] * v2 + w[4] * cr2) * inv;
            float* dst = g_agg + ((long)rc * 32 + lane) * 4;
            asm volatile("red.global.add.v4.f32 [%0], {%1,%2,%3,%4};"
                         :: "l"(dst), "f"(ms), "f"(m0), "f"(m1), "f"(m2)
                         : "memory");
        }
    }
}

// ---- scalar branch: partial pre_s, f-split across blockIdx.y ----------------
#define NS_SMEM_FLOATS 29056
__global__ __launch_bounds__(256, 1) void k_node_s(const float* __restrict__ attrs,
                                                   const float* __restrict__ linWs,
                                                   const float* __restrict__ scWs, int l) {
    extern __shared__ float sm[];
    float* at_sm = sm;            // 128*65
    float* s_sm = sm + 8320;      // 128*17
    float* Zf = sm + 10496;       // 128*65
    float* lw = sm + 18816;       // 2048
    float* Wbuf = sm + 20864;     // 2*4096
    int t = threadIdx.x;
    int nb = blockIdx.x * 128;
    int chunk = blockIdx.y;
    int f0 = chunk * 16;
    const float* lWs = linWs + l * 2048;
    const float* sWs = scWs + l * 131072;
    for (int i = t; i < 8192; i += 256) {
        int n = i >> 6, a = i & 63;
        at_sm[n * 65 + a] = ((nb + n) < NN) ? attrs[(nb + n) * 64 + a] : 0.f;
    }
    for (int i = t; i < 2048; i += 256) {
        int n = i >> 4, fl = i & 15;
        s_sm[n * 17 + fl] = ((nb + n) < NN) ? g_s[(nb + n) * 32 + f0 + fl] : 0.f;
    }
    if (chunk == 0) {
        for (int i = t; i < 4096; i += 256) {
            int n = i >> 5, f = i & 31;
            Zf[n * 33 + f] = ((nb + n) < NN) ? g_agg[((long)(nb + n) * 32 + f) * 4] : 0.f;
        }
        for (int i = t; i < 2048; i += 256) lw[i] = lWs[i];
    }
    {
        const float* src = sWs + (long)f0 * 4096;
        for (int k = 0; k < 4; k++)
            cpa16(Wbuf + (t + k * 256) * 4, src + (t + k * 256) * 4);
        cpa_commit();
    }
    int tx = t & 15, ty = t >> 4;
    int n0 = ty * 8, c0 = tx * 4;
    ull acc[8][2];
#pragma unroll
    for (int i = 0; i < 8; i++) { acc[i][0] = 0ull; acc[i][1] = 0ull; }
    __syncthreads();
    if (chunk == 0) {
        for (int f = 0; f < 32; f++) {
            float4 w = *(const float4*)&lw[f * 64 + c0];
            ull wlo = pk2(w.x, w.y), whi = pk2(w.z, w.w);
#pragma unroll
            for (int i = 0; i < 8; i++) {
                float p = Zf[(n0 + i) * 33 + f];
                ull pp = pk2(p, p);
                ffma2(acc[i][0], pp, wlo);
                ffma2(acc[i][1], pp, whi);
            }
        }
    }
    for (int fi = 0; fi < 16; fi++) {
        __syncthreads();
        if (fi + 1 < 16) {
            float* dst = Wbuf + ((fi + 1) & 1) * 4096;
            const float* src = sWs + (long)(f0 + fi + 1) * 4096;
            for (int k = 0; k < 4; k++)
                cpa16(dst + (t + k * 256) * 4, src + (t + k * 256) * 4);
            cpa_commit();
        }
        for (int i = t; i < 8192; i += 256) {
            int n = i >> 6, a = i & 63;
            Zf[n * 65 + a] = s_sm[n * 17 + fi] * at_sm[n * 65 + a];
        }
        if (fi + 1 < 16) cpa_wait<1>(); else cpa_wait<0>();
        __syncthreads();
        const float* W = Wbuf + (fi & 1) * 4096;
#pragma unroll 2
        for (int a = 0; a < 64; a++) {
            float4 w = *(const float4*)&W[a * 64 + c0];
            ull wlo = pk2(w.x, w.y), whi = pk2(w.z, w.w);
#pragma unroll
            for (int i = 0; i < 8; i++) {
                float p = Zf[(n0 + i) * 65 + a];
                ull pp = pk2(p, p);
                ffma2(acc[i][0], pp, wlo);
                ffma2(acc[i][1], pp, whi);
            }
        }
    }
#pragma unroll
    for (int i = 0; i < 8; i++) {
        int n = nb + n0 + i;
        if (n >= NN) continue;
        float p0, p1, p2, p3;
        upk2(acc[i][0], p0, p1);
        upk2(acc[i][1], p2, p3);
        float* dst = g_pre_s + (long)n * 64 + c0;
        asm volatile("red.global.add.v4.f32 [%0], {%1,%2,%3,%4};"
                     :: "l"(dst), "f"(p0), "f"(p1), "f"(p2), "f"(p3)
                     : "memory");
    }
}

// ---- scalar finalize --------------------------------------------------------
__global__ void k_fin_s() {
    int i = blockIdx.x * blockDim.x + threadIdx.x;
    if (i >= NN * 32) return;
    int n = i >> 5, f = i & 31;
    float a = g_pre_s[n * 64 + f];
    float b = g_pre_s[n * 64 + 32 + f];
    g_gate[i] = 1.f / (1.f + __expf(-b));
    g_s[i] = g_s[i] + a / (1.f + __expf(-a));
}

// ---- vector branch: T-factorized einsum -------------------------------------
#define NV_SMEM_FLOATS 45504
__global__ __launch_bounds__(256, 1) void k_node_v(const float* __restrict__ attrs,
                                                   const float* __restrict__ linWv,
                                                   const float* __restrict__ scWv, int l) {
    extern __shared__ float sm[];
    float* at_sm = sm;            // 64*65
    float* v_sm = sm + 4160;      // 192*33
    float* av_sm = sm + 10496;    // 192*33
    float* T = sm + 16832;        // 256*36
    float* lw = sm + 26048;       // 1024
    float* gt_sm = sm + 27072;    // 2048
    float* Wbuf = sm + 29120;     // 2*8192
    int t = threadIdx.x;
    int nb = blockIdx.x * 64;
    const float* lW = linWv + l * 1024;
    const float* sW = scWv + l * 65536;
    for (int i = t; i < 64 * 96; i += 256) {
        int n = i / 96, r = i % 96, c = r >> 5, f = r & 31;
        bool ok = (nb + n) < NN;
        v_sm[(n * 3 + c) * 33 + f] = ok ? g_v[(nb + n) * 96 + c * 32 + f] : 0.f;
        av_sm[(n * 3 + c) * 33 + f] = ok ? g_agg[((long)(nb + n) * 32 + f) * 4 + 1 + c] : 0.f;
    }
    for (int i = t; i < 4096; i += 256) {
        int n = i >> 6, a = i & 63;
        at_sm[n * 65 + a] = ((nb + n) < NN) ? attrs[(nb + n) * 64 + a] : 0.f;
    }
    for (int i = t; i < 2048; i += 256) {
        int n = i >> 5;
        gt_sm[i] = ((nb + n) < NN) ? g_gate[(nb + n) * 32 + (i & 31)] : 0.f;
    }
    for (int i = t; i < 1024; i += 256) lw[i] = lW[i];
    {
        for (int k = 0; k < 8; k++)
            cpa16(Wbuf + (t + k * 256) * 4, sW + (t + k * 256) * 4);
        cpa_commit();
    }
    int tyB = t >> 3;
    int g0 = (t & 7) * 4;
    int n0 = tyB * 2;
    ull acc[2][3][2];
#pragma unroll
    for (int i = 0; i < 2; i++)
#pragma unroll
        for (int c = 0; c < 3; c++) { acc[i][c][0] = 0ull; acc[i][c][1] = 0ull; }
    __syncthreads();
    for (int f = 0; f < 32; f++) {
        float4 w = *(const float4*)&lw[f * 32 + g0];
        ull wlo = pk2(w.x, w.y), whi = pk2(w.z, w.w);
#pragma unroll
        for (int i = 0; i < 2; i++)
#pragma unroll
            for (int c = 0; c < 3; c++) {
                float p = av_sm[((n0 + i) * 3 + c) * 33 + f];
                ull pp = pk2(p, p);
                ffma2(acc[i][c][0], pp, wlo);
                ffma2(acc[i][c][1], pp, whi);
            }
    }
    int fl1 = tyB >> 3;
    int n0p = (tyB & 7) * 8;
    for (int ch = 0; ch < 8; ch++) {
        __syncthreads();
        if (ch + 1 < 8) {
            float* dst = Wbuf + ((ch + 1) & 1) * 8192;
            const float* src = sW + (long)(ch + 1) * 8192;
            for (int k = 0; k < 8; k++)
                cpa16(dst + (t + k * 256) * 4, src + (t + k * 256) * 4);
            cpa_commit();
        }
        if (ch + 1 < 8) cpa_wait<1>(); else cpa_wait<0>();
        __syncthreads();
        {
            const float* W = Wbuf + (ch & 1) * 8192;
            ull tacc[8][2];
#pragma unroll
            for (int i = 0; i < 8; i++) { tacc[i][0] = 0ull; tacc[i][1] = 0ull; }
#pragma unroll 2
            for (int a = 0; a < 64; a++) {
                float4 w = *(const float4*)&W[(fl1 * 64 + a) * 32 + g0];
                ull wlo = pk2(w.x, w.y), whi = pk2(w.z, w.w);
#pragma unroll
                for (int i = 0; i < 8; i++) {
                    float p = at_sm[(n0p + i) * 65 + a];
                    ull pp = pk2(p, p);
                    ffma2(tacc[i][0], pp, wlo);
                    ffma2(tacc[i][1], pp, whi);
                }
            }
#pragma unroll
            for (int i = 0; i < 8; i++) {
                float p0, p1, p2, p3;
                upk2(tacc[i][0], p0, p1);
                upk2(tacc[i][1], p2, p3);
                *(float4*)&T[((n0p + i) * 4 + fl1) * 36 + g0] = make_float4(p0, p1, p2, p3);
            }
        }
        __syncthreads();
#pragma unroll
        for (int fl = 0; fl < 4; fl++) {
            int f = ch * 4 + fl;
#pragma unroll
            for (int i = 0; i < 2; i++) {
                const float* Tr = &T[((n0 + i) * 4 + fl) * 36 + g0];
                ull t0 = *(const ull*)Tr;
                ull t1 = *(const ull*)(Tr + 2);
#pragma unroll
                for (int c = 0; c < 3; c++) {
                    float p = v_sm[((n0 + i) * 3 + c) * 33 + f];
                    ull pp = pk2(p, p);
                    ffma2(acc[i][c][0], pp, t0);
                    ffma2(acc[i][c][1], pp, t1);
                }
            }
        }
    }
#pragma unroll
    for (int i = 0; i < 2; i++) {
        int n = nb + n0 + i;
        if (n >= NN) continue;
#pragma unroll
        for (int c = 0; c < 3; c++) {
            float p0, p1, p2, p3;
            upk2(acc[i][c][0], p0, p1);
            upk2(acc[i][c][1], p2, p3);
            float4 o;
            o.x = p0 * gt_sm[(n0 + i) * 32 + g0 + 0] + v_sm[((n0 + i) * 3 + c) * 33 + g0 + 0];
            o.y = p1 * gt_sm[(n0 + i) * 32 + g0 + 1] + v_sm[((n0 + i) * 3 + c) * 33 + g0 + 1];
            o.z = p2 * gt_sm[(n0 + i) * 32 + g0 + 2] + v_sm[((n0 + i) * 3 + c) * 33 + g0 + 2];
            o.w = p3 * gt_sm[(n0 + i) * 32 + g0 + 3] + v_sm[((n0 + i) * 3 + c) * 33 + g0 + 3];
            *(float4*)&g_v[(long)n * 96 + c * 32 + g0] = o;
        }
    }
}

// ---- output assembly --------------------------------------------------------
__global__ void k_out(float* __restrict__ out) {
    int i = blockIdx.x * blockDim.x + threadIdx.x;
    if (i >= NN * 128) return;
    int n = i >> 7, c = i & 127;
    float val;
    if (c < 32) {
        val = g_s[n * 32 + c];
    } else {
        int k = c - 32;
        int f = k / 3;
        int cc = k - 3 * f;
        val = g_v[n * 96 + cc * 32 + f];
    }
    out[i] = val;
}

// ---- launch -----------------------------------------------------------------
extern "C" void kernel_launch(void* const* d_in, const int* in_sizes, int n_in,
                              void* d_out, int out_size) {
    const float* attrs = (const float*)d_in[0];
    const float* coord = (const float*)d_in[1];
    const int* ei = (const int*)d_in[2];
    const float* embW = (const float*)d_in[3];
    const float* rW1 = (const float*)d_in[4];
    const float* rb1 = (const float*)d_in[5];
    const float* rW2 = (const float*)d_in[6];
    const float* lWs = (const float*)d_in[7];
    const float* lWv = (const float*)d_in[8];
    const float* sWs = (const float*)d_in[9];
    const float* sWv = (const float*)d_in[10];
    (void)in_sizes; (void)n_in; (void)out_size;

    cudaFuncSetAttribute(k_edge, cudaFuncAttributeMaxDynamicSharedMemorySize,
                         EDGE_SMEM_FLOATS * 4);
    cudaFuncSetAttribute(k_node_s, cudaFuncAttributeMaxDynamicSharedMemorySize,
                         NS_SMEM_FLOATS * 4);
    cudaFuncSetAttribute(k_node_v, cudaFuncAttributeMaxDynamicSharedMemorySize,
                         NV_SMEM_FLOATS * 4);

    k_zero_v<<<1875, 256>>>();
    k_geom<<<2500, 256>>>(coord, ei);
    k_embed<<<2500, 256>>>(attrs, embW);
    for (int l = 0; l < 2; l++) {
        k_zero2<<<3750, 256>>>();
        k_edge<<<5000, 256, EDGE_SMEM_FLOATS * 4>>>(ei, rW1, rb1, rW2, l);
        dim3 gs(157, 2);
        k_node_s<<<gs, 256, NS_SMEM_FLOATS * 4>>>(attrs, lWs, sWs, l);
        k_fin_s<<<2500, 256>>>();
        k_node_v<<<313, 256, NV_SMEM_FLOATS * 4>>>(attrs, lWv, sWv, l);
    }
    k_out<<<10000, 256>>>((float*)d_out);
}